// round 2
// baseline (speedup 1.0000x reference)
#include <cuda_runtime.h>
#include <cuda_bf16.h>

// Problem constants (fixed shapes from the reference)
#define Bc     4
#define Sc     2048
#define Dc     512
#define Mc     2048          // clip range
#define Vc     4097          // 2M+1 table rows
#define PMAX   3000          // positions in [0, 3000)
#define NFFT   8192
#define LOG2N  13
#define CPAIRS (Dc/2)        // 256 complex-packed channel pairs
#define FFT_THREADS 512
#define FFT_SMEM (2 * NFFT * (int)sizeof(float2))   // 131072 bytes (ping-pong)

// ---------------------------------------------------------------------------
// Scratch (static device globals; no allocation inside kernel_launch)
// ---------------------------------------------------------------------------
__device__ float  g_cnt[Bc][PMAX];          // per-batch position histogram
__device__ float  g_pre[Bc][PMAX];          // inclusive prefix sums of g_cnt
__device__ float2 g_CNT[Bc][NFFT];          // spectra of cnt
__device__ float2 g_EMB[CPAIRS][NFFT];      // spectra of packed table column pairs
__device__ float  g_G[Bc][PMAX][Dc];        // interior conv result y[q+M] per channel

// ---------------------------------------------------------------------------
// K1: histogram + inclusive prefix scan per batch (one 1024-thread block/batch)
// ---------------------------------------------------------------------------
__global__ void hist_scan_kernel(const int* __restrict__ pos) {
    __shared__ float hist[3072];
    __shared__ float tsum[1024];
    const int b = blockIdx.x;
    const int t = threadIdx.x;

    for (int p = t; p < 3072; p += 1024) hist[p] = 0.0f;
    __syncthreads();
    for (int i = t; i < Sc; i += 1024)
        atomicAdd(&hist[pos[b * Sc + i]], 1.0f);
    __syncthreads();

    // each thread scans 3 consecutive elements
    const float v0 = hist[3 * t + 0];
    const float v1 = hist[3 * t + 1];
    const float v2 = hist[3 * t + 2];
    const float s  = v0 + v1 + v2;
    tsum[t] = s;
    __syncthreads();
    // Hillis-Steele inclusive scan over 1024 thread sums
    for (int off = 1; off < 1024; off <<= 1) {
        const float add = (t >= off) ? tsum[t - off] : 0.0f;
        __syncthreads();
        tsum[t] += add;
        __syncthreads();
    }
    const float excl = tsum[t] - s;
    const int p0 = 3 * t;
    if (p0 + 0 < PMAX) { g_cnt[b][p0 + 0] = v0; g_pre[b][p0 + 0] = excl + v0; }
    if (p0 + 1 < PMAX) { g_cnt[b][p0 + 1] = v1; g_pre[b][p0 + 1] = excl + v0 + v1; }
    if (p0 + 2 < PMAX) { g_cnt[b][p0 + 2] = v2; g_pre[b][p0 + 2] = excl + v0 + v1 + v2; }
}

// ---------------------------------------------------------------------------
// Block FFT: radix-2 Stockham autosort, ping-pong in shared memory.
// sign = -1 forward, +1 inverse (unnormalized). Returns buffer holding result
// in natural order.
// ---------------------------------------------------------------------------
__device__ __forceinline__ float2* block_fft(float2* b0, float2* b1, float sign) {
    float2* src = b0;
    float2* dst = b1;
#pragma unroll 1
    for (int s = 0; s < LOG2N; s++) {
        const int m = 1 << s;
        const int l = (NFFT >> 1) >> s;
        const float ang_scale = sign * 3.14159265358979323846f / (float)l;
        for (int idx = threadIdx.x; idx < (NFFT >> 1); idx += blockDim.x) {
            const int k  = idx & (m - 1);
            const int jm = idx - k;            // j*m
            const int j  = idx >> s;
            const float2 c0 = src[idx];
            const float2 c1 = src[idx + (NFFT >> 1)];
            float sn, cs;
            __sincosf(ang_scale * (float)j, &sn, &cs);
            const float2 sum = make_float2(c0.x + c1.x, c0.y + c1.y);
            const float2 dif = make_float2(c0.x - c1.x, c0.y - c1.y);
            dst[jm + idx]     = sum;                                   // index 2jm+k
            dst[jm + idx + m] = make_float2(cs * dif.x - sn * dif.y,   // index 2jm+k+m
                                            cs * dif.y + sn * dif.x);
        }
        __syncthreads();
        float2* tmp = src; src = dst; dst = tmp;
    }
    return src;   // after odd #stages this is b1, but pointer tracking handles it
}

extern __shared__ float2 smfft[];

// ---------------------------------------------------------------------------
// K2: forward FFT of table column pairs (channel 2c packed as real, 2c+1 imag)
// ---------------------------------------------------------------------------
__global__ void fft_table_kernel(const float* __restrict__ emb) {
    const int c = blockIdx.x;
    float2* b0 = smfft;
    float2* b1 = smfft + NFFT;
    for (int n = threadIdx.x; n < NFFT; n += blockDim.x) {
        float2 v = make_float2(0.0f, 0.0f);
        if (n < Vc) {
            v.x = emb[n * Dc + 2 * c + 0];
            v.y = emb[n * Dc + 2 * c + 1];
        }
        b0[n] = v;
    }
    __syncthreads();
    float2* r = block_fft(b0, b1, -1.0f);
    for (int n = threadIdx.x; n < NFFT; n += blockDim.x)
        g_EMB[c][n] = r[n];
}

// ---------------------------------------------------------------------------
// K3: forward FFT of the per-batch count histograms
// ---------------------------------------------------------------------------
__global__ void fft_cnt_kernel() {
    const int b = blockIdx.x;
    float2* b0 = smfft;
    float2* b1 = smfft + NFFT;
    for (int n = threadIdx.x; n < NFFT; n += blockDim.x) {
        float2 v = make_float2(0.0f, 0.0f);
        if (n < PMAX) v.x = g_cnt[b][n];
        b0[n] = v;
    }
    __syncthreads();
    float2* r = block_fft(b0, b1, -1.0f);
    for (int n = threadIdx.x; n < NFFT; n += blockDim.x)
        g_CNT[b][n] = r[n];
}

// ---------------------------------------------------------------------------
// K4: pointwise spectral multiply + inverse FFT; extract y[q+M] for q in [0,3000)
// real part -> channel 2c, imag part -> channel 2c+1 (cnt is real)
// ---------------------------------------------------------------------------
__global__ void conv_kernel() {
    const int c = blockIdx.x;
    const int b = blockIdx.y;
    float2* b0 = smfft;
    float2* b1 = smfft + NFFT;
    for (int n = threadIdx.x; n < NFFT; n += blockDim.x) {
        const float2 e = g_EMB[c][n];
        const float2 t = g_CNT[b][n];
        b0[n] = make_float2(e.x * t.x - e.y * t.y,
                            e.x * t.y + e.y * t.x);
    }
    __syncthreads();
    float2* r = block_fft(b0, b1, +1.0f);
    const float inv = 1.0f / (float)NFFT;
    for (int q = threadIdx.x; q < PMAX; q += blockDim.x) {
        const float2 y = r[q + Mc];
        g_G[b][q][2 * c + 0] = y.x * inv;
        g_G[b][q][2 * c + 1] = y.y * inv;
    }
}

// ---------------------------------------------------------------------------
// K5: gather per output row + clamp-tail correction + add x, write out.
// out[b,i,d] = x + (G[b,q,d] + a0*emb[0,d] + a1*emb[V-1,d]) / S
//   a0 = #(p > q+M) = S - pre[min(q+M, PMAX-1)]
//   a1 = #(p < q-M) = (q >= M+1) ? pre[q-M-1] : 0
// ---------------------------------------------------------------------------
__global__ void epilogue_kernel(const float4* __restrict__ x,
                                const float*  __restrict__ emb,
                                const int*    __restrict__ pos,
                                float4*       __restrict__ out) {
    const int v = blockIdx.x * blockDim.x + threadIdx.x;   // [0, B*S*D/4)
    const int d4  = v & (Dc / 4 - 1);            // 0..127
    const int row = v >> 7;                      // 0..8191
    const int b   = row >> 11;
    const int q   = pos[row];

    const float a0 = (float)Sc - g_pre[b][min(q + Mc, PMAX - 1)];
    const float a1 = (q >= Mc + 1) ? g_pre[b][q - Mc - 1] : 0.0f;
    const float invS = 1.0f / (float)Sc;

    const float4 xv = x[v];
    const float4 g  = *reinterpret_cast<const float4*>(&g_G[b][q][d4 * 4]);
    const float4 e0 = *reinterpret_cast<const float4*>(&emb[0 * Dc + d4 * 4]);
    const float4 e1 = *reinterpret_cast<const float4*>(&emb[(Vc - 1) * Dc + d4 * 4]);

    float4 o;
    o.x = xv.x + (g.x + a0 * e0.x + a1 * e1.x) * invS;
    o.y = xv.y + (g.y + a0 * e0.y + a1 * e1.y) * invS;
    o.z = xv.z + (g.z + a0 * e0.z + a1 * e1.z) * invS;
    o.w = xv.w + (g.w + a0 * e0.w + a1 * e1.w) * invS;
    out[v] = o;
}

// ---------------------------------------------------------------------------
// Launch
// ---------------------------------------------------------------------------
extern "C" void kernel_launch(void* const* d_in, const int* in_sizes, int n_in,
                              void* d_out, int out_size) {
    const float* x   = (const float*)d_in[0];
    const float* emb = (const float*)d_in[1];
    const int*   pos = (const int*)d_in[2];
    float*       out = (float*)d_out;

    cudaFuncSetAttribute(fft_table_kernel, cudaFuncAttributeMaxDynamicSharedMemorySize, FFT_SMEM);
    cudaFuncSetAttribute(fft_cnt_kernel,   cudaFuncAttributeMaxDynamicSharedMemorySize, FFT_SMEM);
    cudaFuncSetAttribute(conv_kernel,      cudaFuncAttributeMaxDynamicSharedMemorySize, FFT_SMEM);

    hist_scan_kernel<<<Bc, 1024>>>(pos);
    fft_table_kernel<<<CPAIRS, FFT_THREADS, FFT_SMEM>>>(emb);
    fft_cnt_kernel<<<Bc, FFT_THREADS, FFT_SMEM>>>();
    conv_kernel<<<dim3(CPAIRS, Bc), FFT_THREADS, FFT_SMEM>>>();

    const int total_vec = Bc * Sc * Dc / 4;    // 1,048,576
    epilogue_kernel<<<total_vec / 256, 256>>>((const float4*)x, emb, pos, (float4*)out);
}

// round 3
// speedup vs baseline: 1.2319x; 1.2319x over previous
#include <cuda_runtime.h>
#include <cuda_bf16.h>

// Problem constants (fixed shapes from the reference)
#define Bc     4
#define Sc     2048
#define Dc     512
#define Mc     2048          // clip range
#define Vc     4097          // 2M+1 table rows
#define PMAX   3000          // positions in [0, 3000)
#define NFFT   8192
#define CPAIRS (Dc/2)        // 256 complex-packed channel pairs
#define FFT_THREADS 512
// smem: ping-pong (2 x 8192 float2) + twiddle LUT (2048 float2) = 144 KB
#define LUT_N  2048
#define FFT_SMEM ((2 * NFFT + LUT_N) * (int)sizeof(float2))

// ---------------------------------------------------------------------------
// Scratch (static device globals; no allocation inside kernel_launch)
// ---------------------------------------------------------------------------
__device__ float  g_cnt[Bc][PMAX];          // per-batch position histogram
__device__ float  g_pre[Bc][PMAX];          // inclusive prefix sums of g_cnt
__device__ float2 g_CNT[Bc][NFFT];          // spectra of cnt
__device__ float2 g_EMB[CPAIRS][NFFT];      // spectra of packed table column pairs
__device__ float  g_G[Bc][PMAX][Dc];        // interior conv result y[q+M] per channel

__device__ __forceinline__ float2 cmul(float2 a, float2 b) {
    return make_float2(a.x * b.x - a.y * b.y, a.x * b.y + a.y * b.x);
}
__device__ __forceinline__ float2 cadd(float2 a, float2 b) {
    return make_float2(a.x + b.x, a.y + b.y);
}
__device__ __forceinline__ float2 csub(float2 a, float2 b) {
    return make_float2(a.x - b.x, a.y - b.y);
}

// ---------------------------------------------------------------------------
// K1: histogram + inclusive prefix scan per batch (one 1024-thread block/batch)
// ---------------------------------------------------------------------------
__global__ void hist_scan_kernel(const int* __restrict__ pos) {
    __shared__ float hist[3072];
    __shared__ float tsum[1024];
    const int b = blockIdx.x;
    const int t = threadIdx.x;

    for (int p = t; p < 3072; p += 1024) hist[p] = 0.0f;
    __syncthreads();
    for (int i = t; i < Sc; i += 1024)
        atomicAdd(&hist[pos[b * Sc + i]], 1.0f);
    __syncthreads();

    const float v0 = hist[3 * t + 0];
    const float v1 = hist[3 * t + 1];
    const float v2 = hist[3 * t + 2];
    const float s  = v0 + v1 + v2;
    tsum[t] = s;
    __syncthreads();
    for (int off = 1; off < 1024; off <<= 1) {
        const float add = (t >= off) ? tsum[t - off] : 0.0f;
        __syncthreads();
        tsum[t] += add;
        __syncthreads();
    }
    const float excl = tsum[t] - s;
    const int p0 = 3 * t;
    if (p0 + 0 < PMAX) { g_cnt[b][p0 + 0] = v0; g_pre[b][p0 + 0] = excl + v0; }
    if (p0 + 1 < PMAX) { g_cnt[b][p0 + 1] = v1; g_pre[b][p0 + 1] = excl + v0 + v1; }
    if (p0 + 2 < PMAX) { g_cnt[b][p0 + 2] = v2; g_pre[b][p0 + 2] = excl + v0 + v1 + v2; }
}

// ---------------------------------------------------------------------------
// Twiddle LUT: lut[t] = exp(-2*pi*i*t/NFFT), t in [0, NFFT/4)
// ---------------------------------------------------------------------------
__device__ __forceinline__ void build_lut(float2* lut) {
    const float w = -6.283185307179586f / (float)NFFT;
    for (int t = threadIdx.x; t < LUT_N; t += blockDim.x) {
        float sn, cs;
        __sincosf(w * (float)t, &sn, &cs);
        lut[t] = make_float2(cs, sn);
    }
}

// ---------------------------------------------------------------------------
// Block FFT: Stockham autosort, 6 radix-4 stages + 1 radix-2 stage.
// INV=false: forward (sign -1). INV=true: inverse (unnormalized).
// Requires prior __syncthreads covering data + LUT population.
// Returns the buffer holding the natural-order result.
// ---------------------------------------------------------------------------
template <bool INV>
__device__ float2* block_fft(float2* b0, float2* b1, const float2* __restrict__ lut) {
    float2* src = b0;
    float2* dst = b1;
    int m = 1;
#pragma unroll 1
    for (int s = 0; s < 6; s++) {
        for (int idx = threadIdx.x; idx < (NFFT / 4); idx += FFT_THREADS) {
            const int k  = idx & (m - 1);
            const int jm = idx - k;                 // j*m, < NFFT/4
            const float2 x0 = src[idx];
            const float2 x1 = src[idx + 1 * (NFFT / 4)];
            const float2 x2 = src[idx + 2 * (NFFT / 4)];
            const float2 x3 = src[idx + 3 * (NFFT / 4)];

            float2 u = lut[jm];
            if (INV) u.y = -u.y;
            const float2 u2 = cmul(u, u);
            const float2 u3 = cmul(u2, u);

            const float2 ta = cadd(x0, x2);
            const float2 tc = csub(x0, x2);
            const float2 tb = cadd(x1, x3);
            const float2 xd = csub(x1, x3);
            // td = sign*i*(x1-x3): forward sign=-1 -> (xd.y, -xd.x); inverse -> (-xd.y, xd.x)
            const float2 td = INV ? make_float2(-xd.y, xd.x)
                                  : make_float2(xd.y, -xd.x);

            const int ob = idx + 3 * jm;            // 4*j*m + k
            dst[ob + 0 * m] = cadd(ta, tb);
            dst[ob + 1 * m] = cmul(u,  cadd(tc, td));
            dst[ob + 2 * m] = cmul(u2, csub(ta, tb));
            dst[ob + 3 * m] = cmul(u3, csub(tc, td));
        }
        __syncthreads();
        float2* tmp = src; src = dst; dst = tmp;
        m <<= 2;
    }
    // final radix-2 stage: m = 4096, l = 1, twiddle = 1
    for (int idx = threadIdx.x; idx < (NFFT / 2); idx += FFT_THREADS) {
        const float2 a = src[idx];
        const float2 b = src[idx + NFFT / 2];
        dst[idx]            = cadd(a, b);
        dst[idx + NFFT / 2] = csub(a, b);
    }
    __syncthreads();
    return dst;
}

extern __shared__ float2 smfft[];

// ---------------------------------------------------------------------------
// K2: forward FFT of table column pairs (channel 2c packed real, 2c+1 imag)
// ---------------------------------------------------------------------------
__global__ void fft_table_kernel(const float* __restrict__ emb) {
    const int c = blockIdx.x;
    float2* b0  = smfft;
    float2* b1  = smfft + NFFT;
    float2* lut = smfft + 2 * NFFT;
    build_lut(lut);
    for (int n = threadIdx.x; n < NFFT; n += blockDim.x) {
        float2 v = make_float2(0.0f, 0.0f);
        if (n < Vc) {
            v.x = emb[n * Dc + 2 * c + 0];
            v.y = emb[n * Dc + 2 * c + 1];
        }
        b0[n] = v;
    }
    __syncthreads();
    float2* r = block_fft<false>(b0, b1, lut);
    for (int n = threadIdx.x; n < NFFT; n += blockDim.x)
        g_EMB[c][n] = r[n];
}

// ---------------------------------------------------------------------------
// K3: forward FFT of the per-batch count histograms
// ---------------------------------------------------------------------------
__global__ void fft_cnt_kernel() {
    const int b = blockIdx.x;
    float2* b0  = smfft;
    float2* b1  = smfft + NFFT;
    float2* lut = smfft + 2 * NFFT;
    build_lut(lut);
    for (int n = threadIdx.x; n < NFFT; n += blockDim.x) {
        float2 v = make_float2(0.0f, 0.0f);
        if (n < PMAX) v.x = g_cnt[b][n];
        b0[n] = v;
    }
    __syncthreads();
    float2* r = block_fft<false>(b0, b1, lut);
    for (int n = threadIdx.x; n < NFFT; n += blockDim.x)
        g_CNT[b][n] = r[n];
}

// ---------------------------------------------------------------------------
// K4: pointwise spectral multiply + inverse FFT; extract y[q+M], q in [0,3000)
// real part -> channel 2c, imag part -> channel 2c+1 (cnt is real)
// ---------------------------------------------------------------------------
__global__ void conv_kernel() {
    const int c = blockIdx.x;
    const int b = blockIdx.y;
    float2* b0  = smfft;
    float2* b1  = smfft + NFFT;
    float2* lut = smfft + 2 * NFFT;
    build_lut(lut);
    const float2* __restrict__ E = g_EMB[c];
    const float2* __restrict__ T = g_CNT[b];
    for (int n = threadIdx.x; n < NFFT; n += blockDim.x) {
        const float2 e = E[n];
        const float2 t = T[n];
        b0[n] = make_float2(e.x * t.x - e.y * t.y,
                            e.x * t.y + e.y * t.x);
    }
    __syncthreads();
    float2* r = block_fft<true>(b0, b1, lut);
    const float inv = 1.0f / (float)NFFT;
    for (int q = threadIdx.x; q < PMAX; q += blockDim.x) {
        const float2 y = r[q + Mc];
        g_G[b][q][2 * c + 0] = y.x * inv;
        g_G[b][q][2 * c + 1] = y.y * inv;
    }
}

// ---------------------------------------------------------------------------
// K5: gather per output row + clamp-tail correction + add x, write out.
// out[b,i,d] = x + (G[b,q,d] + a0*emb[0,d] + a1*emb[V-1,d]) / S
//   a0 = #(p > q+M) = S - pre[min(q+M, PMAX-1)]
//   a1 = #(p < q-M) = (q >= M+1) ? pre[q-M-1] : 0
// ---------------------------------------------------------------------------
__global__ void epilogue_kernel(const float4* __restrict__ x,
                                const float*  __restrict__ emb,
                                const int*    __restrict__ pos,
                                float4*       __restrict__ out) {
    const int v = blockIdx.x * blockDim.x + threadIdx.x;   // [0, B*S*D/4)
    const int d4  = v & (Dc / 4 - 1);            // 0..127
    const int row = v >> 7;                      // 0..8191
    const int b   = row >> 11;
    const int q   = pos[row];

    const float a0 = (float)Sc - g_pre[b][min(q + Mc, PMAX - 1)];
    const float a1 = (q >= Mc + 1) ? g_pre[b][q - Mc - 1] : 0.0f;
    const float invS = 1.0f / (float)Sc;

    const float4 xv = x[v];
    const float4 g  = *reinterpret_cast<const float4*>(&g_G[b][q][d4 * 4]);
    const float4 e0 = *reinterpret_cast<const float4*>(&emb[0 * Dc + d4 * 4]);
    const float4 e1 = *reinterpret_cast<const float4*>(&emb[(Vc - 1) * Dc + d4 * 4]);

    float4 o;
    o.x = xv.x + (g.x + a0 * e0.x + a1 * e1.x) * invS;
    o.y = xv.y + (g.y + a0 * e0.y + a1 * e1.y) * invS;
    o.z = xv.z + (g.z + a0 * e0.z + a1 * e1.z) * invS;
    o.w = xv.w + (g.w + a0 * e0.w + a1 * e1.w) * invS;
    out[v] = o;
}

// ---------------------------------------------------------------------------
// Launch
// ---------------------------------------------------------------------------
extern "C" void kernel_launch(void* const* d_in, const int* in_sizes, int n_in,
                              void* d_out, int out_size) {
    const float* x   = (const float*)d_in[0];
    const float* emb = (const float*)d_in[1];
    const int*   pos = (const int*)d_in[2];
    float*       out = (float*)d_out;

    cudaFuncSetAttribute(fft_table_kernel, cudaFuncAttributeMaxDynamicSharedMemorySize, FFT_SMEM);
    cudaFuncSetAttribute(fft_cnt_kernel,   cudaFuncAttributeMaxDynamicSharedMemorySize, FFT_SMEM);
    cudaFuncSetAttribute(conv_kernel,      cudaFuncAttributeMaxDynamicSharedMemorySize, FFT_SMEM);

    hist_scan_kernel<<<Bc, 1024>>>(pos);
    fft_table_kernel<<<CPAIRS, FFT_THREADS, FFT_SMEM>>>(emb);
    fft_cnt_kernel<<<Bc, FFT_THREADS, FFT_SMEM>>>();
    conv_kernel<<<dim3(CPAIRS, Bc), FFT_THREADS, FFT_SMEM>>>();

    const int total_vec = Bc * Sc * Dc / 4;    // 1,048,576
    epilogue_kernel<<<total_vec / 256, 256>>>((const float4*)x, emb, pos, (float4*)out);
}

// round 4
// speedup vs baseline: 1.4417x; 1.1703x over previous
#include <cuda_runtime.h>
#include <cuda_bf16.h>

// Problem constants (fixed shapes from the reference)
#define Bc     4
#define Sc     2048
#define Dc     512
#define Mc     2048          // clip range
#define Vc     4097          // 2M+1 table rows
#define PMAX   3000          // positions in [0, 3000)
#define NFFT   8192
#define CPAIRS (Dc/2)        // 256 complex-packed channel pairs
#define FFT_THREADS 1024
#define LUT_N  1024                         // u = W^jm, jm < NFFT/8
#define PADN   (NFFT + (NFFT >> 4))         // 8704 float2 per buffer
#define MAP(i) ((i) + ((i) >> 4))           // bank-conflict-free pad
#define FFT_SMEM ((2 * PADN + LUT_N) * (int)sizeof(float2))   // 147456 B

// ---------------------------------------------------------------------------
// Scratch (static device globals; no allocation inside kernel_launch)
// ---------------------------------------------------------------------------
__device__ float  g_cnt[Bc][PMAX];          // per-batch position histogram
__device__ float  g_pre[Bc][PMAX];          // inclusive prefix sums of g_cnt
__device__ float2 g_CNT[Bc][NFFT];          // spectra of cnt
__device__ float2 g_EMB[CPAIRS][NFFT];      // spectra of packed table column pairs
__device__ float  g_G[Bc][PMAX][Dc];        // interior conv result y[q+M] per channel

__device__ __forceinline__ float2 cmul(float2 a, float2 b) {
    return make_float2(a.x * b.x - a.y * b.y, a.x * b.y + a.y * b.x);
}
__device__ __forceinline__ float2 cadd(float2 a, float2 b) {
    return make_float2(a.x + b.x, a.y + b.y);
}
__device__ __forceinline__ float2 csub(float2 a, float2 b) {
    return make_float2(a.x - b.x, a.y - b.y);
}
// multiply by -i (forward) / +i (inverse)
template <bool INV>
__device__ __forceinline__ float2 mul_mi(float2 v) {
    return INV ? make_float2(-v.y, v.x) : make_float2(v.y, -v.x);
}
#define RSQRT2 0.70710678118654752f
// multiply by W8^1: fwd (1-i)/sqrt2, inv (1+i)/sqrt2
template <bool INV>
__device__ __forceinline__ float2 mul_w1(float2 v) {
    return INV ? make_float2((v.x - v.y) * RSQRT2, (v.y + v.x) * RSQRT2)
               : make_float2((v.x + v.y) * RSQRT2, (v.y - v.x) * RSQRT2);
}
// multiply by W8^3: fwd (-1-i)/sqrt2, inv (-1+i)/sqrt2
template <bool INV>
__device__ __forceinline__ float2 mul_w3(float2 v) {
    return INV ? make_float2((-v.x - v.y) * RSQRT2, (v.x - v.y) * RSQRT2)
               : make_float2((v.y - v.x) * RSQRT2, (-v.x - v.y) * RSQRT2);
}

// ---------------------------------------------------------------------------
// K1: histogram + inclusive prefix scan per batch (one 1024-thread block/batch)
// ---------------------------------------------------------------------------
__global__ void hist_scan_kernel(const int* __restrict__ pos) {
    __shared__ float hist[3072];
    __shared__ float tsum[1024];
    const int b = blockIdx.x;
    const int t = threadIdx.x;

    for (int p = t; p < 3072; p += 1024) hist[p] = 0.0f;
    __syncthreads();
    for (int i = t; i < Sc; i += 1024)
        atomicAdd(&hist[pos[b * Sc + i]], 1.0f);
    __syncthreads();

    const float v0 = hist[3 * t + 0];
    const float v1 = hist[3 * t + 1];
    const float v2 = hist[3 * t + 2];
    const float s  = v0 + v1 + v2;
    tsum[t] = s;
    __syncthreads();
    for (int off = 1; off < 1024; off <<= 1) {
        const float add = (t >= off) ? tsum[t - off] : 0.0f;
        __syncthreads();
        tsum[t] += add;
        __syncthreads();
    }
    const float excl = tsum[t] - s;
    const int p0 = 3 * t;
    if (p0 + 0 < PMAX) { g_cnt[b][p0 + 0] = v0; g_pre[b][p0 + 0] = excl + v0; }
    if (p0 + 1 < PMAX) { g_cnt[b][p0 + 1] = v1; g_pre[b][p0 + 1] = excl + v0 + v1; }
    if (p0 + 2 < PMAX) { g_cnt[b][p0 + 2] = v2; g_pre[b][p0 + 2] = excl + v0 + v1 + v2; }
}

// ---------------------------------------------------------------------------
// Twiddle LUT: lut[t] = exp(-2*pi*i*t/NFFT), t in [0, NFFT/8)
// ---------------------------------------------------------------------------
__device__ __forceinline__ void build_lut(float2* lut) {
    const float w = -6.283185307179586f / (float)NFFT;
    const int t = threadIdx.x;
    if (t < LUT_N) {
        float sn, cs;
        __sincosf(w * (float)t, &sn, &cs);
        lut[t] = make_float2(cs, sn);
    }
}

// ---------------------------------------------------------------------------
// Block FFT: Stockham autosort, 4 radix-8 stages + 1 twiddle-free radix-2.
// 1024 threads, one radix-8 butterfly per thread per stage.
// All ping-pong accesses go through MAP() (bank-conflict-free pad).
// Caller must __syncthreads() after populating src (and LUT).
// ---------------------------------------------------------------------------
template <bool INV>
__device__ float2* block_fft8(float2* b0, float2* b1, const float2* __restrict__ lut) {
    float2* src = b0;
    float2* dst = b1;
    const int t = threadIdx.x;
#pragma unroll
    for (int s = 0; s < 4; s++) {
        const int m  = 1 << (3 * s);           // 1, 8, 64, 512 (compile-time)
        const int k  = t & (m - 1);
        const int jm = t - k;                  // j*m, < 1024

        const float2 x0 = src[MAP(t + 0 * 1024)];
        const float2 x1 = src[MAP(t + 1 * 1024)];
        const float2 x2 = src[MAP(t + 2 * 1024)];
        const float2 x3 = src[MAP(t + 3 * 1024)];
        const float2 x4 = src[MAP(t + 4 * 1024)];
        const float2 x5 = src[MAP(t + 5 * 1024)];
        const float2 x6 = src[MAP(t + 6 * 1024)];
        const float2 x7 = src[MAP(t + 7 * 1024)];

        // E = DFT4(x0,x2,x4,x6)
        const float2 t0 = cadd(x0, x4);
        const float2 t1 = csub(x0, x4);
        const float2 t2 = cadd(x2, x6);
        const float2 t3 = mul_mi<INV>(csub(x2, x6));
        const float2 E0 = cadd(t0, t2);
        const float2 E1 = cadd(t1, t3);
        const float2 E2 = csub(t0, t2);
        const float2 E3 = csub(t1, t3);
        // O = DFT4(x1,x3,x5,x7), then * W8^t
        const float2 s0 = cadd(x1, x5);
        const float2 s1 = csub(x1, x5);
        const float2 s2 = cadd(x3, x7);
        const float2 s3 = mul_mi<INV>(csub(x3, x7));
        const float2 O0 = cadd(s0, s2);
        const float2 O1 = mul_w1<INV>(cadd(s1, s3));
        const float2 O2 = mul_mi<INV>(csub(s0, s2));
        const float2 O3 = mul_w3<INV>(csub(s1, s3));

        float2 u = lut[jm];
        if (INV) u.y = -u.y;
        const float2 u2 = cmul(u, u);
        const float2 u3 = cmul(u2, u);
        const float2 u4 = cmul(u2, u2);
        const float2 u5 = cmul(u3, u2);
        const float2 u6 = cmul(u3, u3);
        const float2 u7 = cmul(u4, u3);

        const int ob = t + 7 * jm;             // 8*j*m + k
        dst[MAP(ob + 0 * m)] = cadd(E0, O0);
        dst[MAP(ob + 1 * m)] = cmul(u,  cadd(E1, O1));
        dst[MAP(ob + 2 * m)] = cmul(u2, cadd(E2, O2));
        dst[MAP(ob + 3 * m)] = cmul(u3, cadd(E3, O3));
        dst[MAP(ob + 4 * m)] = cmul(u4, csub(E0, O0));
        dst[MAP(ob + 5 * m)] = cmul(u5, csub(E1, O1));
        dst[MAP(ob + 6 * m)] = cmul(u6, csub(E2, O2));
        dst[MAP(ob + 7 * m)] = cmul(u7, csub(E3, O3));
        __syncthreads();
        float2* tmp = src; src = dst; dst = tmp;
    }
    // final radix-2 stage: m = 4096, twiddle = 1 (jm = 0)
#pragma unroll
    for (int r = 0; r < 4; r++) {
        const int i = t + r * 1024;
        const float2 a = src[MAP(i)];
        const float2 b = src[MAP(i + 4096)];
        dst[MAP(i)]        = cadd(a, b);
        dst[MAP(i + 4096)] = csub(a, b);
    }
    __syncthreads();
    return dst;
}

extern __shared__ float2 smfft[];

// ---------------------------------------------------------------------------
// K2: forward FFT of table column pairs (channel 2c packed real, 2c+1 imag)
// ---------------------------------------------------------------------------
__global__ void __launch_bounds__(FFT_THREADS, 1)
fft_table_kernel(const float* __restrict__ emb) {
    const int c = blockIdx.x;
    float2* b0  = smfft;
    float2* b1  = smfft + PADN;
    float2* lut = smfft + 2 * PADN;
    build_lut(lut);
    for (int n = threadIdx.x; n < NFFT; n += FFT_THREADS) {
        float2 v = make_float2(0.0f, 0.0f);
        if (n < Vc) {
            v.x = emb[n * Dc + 2 * c + 0];
            v.y = emb[n * Dc + 2 * c + 1];
        }
        b0[MAP(n)] = v;
    }
    __syncthreads();
    float2* r = block_fft8<false>(b0, b1, lut);
    for (int n = threadIdx.x; n < NFFT; n += FFT_THREADS)
        g_EMB[c][n] = r[MAP(n)];
}

// ---------------------------------------------------------------------------
// K3: forward FFT of the per-batch count histograms
// ---------------------------------------------------------------------------
__global__ void __launch_bounds__(FFT_THREADS, 1)
fft_cnt_kernel() {
    const int b = blockIdx.x;
    float2* b0  = smfft;
    float2* b1  = smfft + PADN;
    float2* lut = smfft + 2 * PADN;
    build_lut(lut);
    for (int n = threadIdx.x; n < NFFT; n += FFT_THREADS) {
        float2 v = make_float2(0.0f, 0.0f);
        if (n < PMAX) v.x = g_cnt[b][n];
        b0[MAP(n)] = v;
    }
    __syncthreads();
    float2* r = block_fft8<false>(b0, b1, lut);
    for (int n = threadIdx.x; n < NFFT; n += FFT_THREADS)
        g_CNT[b][n] = r[MAP(n)];
}

// ---------------------------------------------------------------------------
// K4: pointwise spectral multiply + inverse FFT; extract y[q+M], q in [0,3000)
// real part -> channel 2c, imag part -> channel 2c+1 (cnt is real)
// ---------------------------------------------------------------------------
__global__ void __launch_bounds__(FFT_THREADS, 1)
conv_kernel() {
    const int c = blockIdx.x;
    const int b = blockIdx.y;
    float2* b0  = smfft;
    float2* b1  = smfft + PADN;
    float2* lut = smfft + 2 * PADN;
    build_lut(lut);
    const float2* __restrict__ E = g_EMB[c];
    const float2* __restrict__ T = g_CNT[b];
    for (int n = threadIdx.x; n < NFFT; n += FFT_THREADS) {
        const float2 e = E[n];
        const float2 t = T[n];
        b0[MAP(n)] = make_float2(e.x * t.x - e.y * t.y,
                                 e.x * t.y + e.y * t.x);
    }
    __syncthreads();
    float2* r = block_fft8<true>(b0, b1, lut);
    const float inv = 1.0f / (float)NFFT;
    for (int q = threadIdx.x; q < PMAX; q += FFT_THREADS) {
        const float2 y = r[MAP(q + Mc)];
        g_G[b][q][2 * c + 0] = y.x * inv;
        g_G[b][q][2 * c + 1] = y.y * inv;
    }
}

// ---------------------------------------------------------------------------
// K5: gather per output row + clamp-tail correction + add x, write out.
// out[b,i,d] = x + (G[b,q,d] + a0*emb[0,d] + a1*emb[V-1,d]) / S
//   a0 = #(p > q+M) = S - pre[min(q+M, PMAX-1)]
//   a1 = #(p < q-M) = (q >= M+1) ? pre[q-M-1] : 0
// ---------------------------------------------------------------------------
__global__ void epilogue_kernel(const float4* __restrict__ x,
                                const float*  __restrict__ emb,
                                const int*    __restrict__ pos,
                                float4*       __restrict__ out) {
    const int v = blockIdx.x * blockDim.x + threadIdx.x;   // [0, B*S*D/4)
    const int d4  = v & (Dc / 4 - 1);            // 0..127
    const int row = v >> 7;                      // 0..8191
    const int b   = row >> 11;
    const int q   = pos[row];

    const float a0 = (float)Sc - g_pre[b][min(q + Mc, PMAX - 1)];
    const float a1 = (q >= Mc + 1) ? g_pre[b][q - Mc - 1] : 0.0f;
    const float invS = 1.0f / (float)Sc;

    const float4 xv = x[v];
    const float4 g  = *reinterpret_cast<const float4*>(&g_G[b][q][d4 * 4]);
    const float4 e0 = *reinterpret_cast<const float4*>(&emb[0 * Dc + d4 * 4]);
    const float4 e1 = *reinterpret_cast<const float4*>(&emb[(Vc - 1) * Dc + d4 * 4]);

    float4 o;
    o.x = xv.x + (g.x + a0 * e0.x + a1 * e1.x) * invS;
    o.y = xv.y + (g.y + a0 * e0.y + a1 * e1.y) * invS;
    o.z = xv.z + (g.z + a0 * e0.z + a1 * e1.z) * invS;
    o.w = xv.w + (g.w + a0 * e0.w + a1 * e1.w) * invS;
    out[v] = o;
}

// ---------------------------------------------------------------------------
// Launch
// ---------------------------------------------------------------------------
extern "C" void kernel_launch(void* const* d_in, const int* in_sizes, int n_in,
                              void* d_out, int out_size) {
    const float* x   = (const float*)d_in[0];
    const float* emb = (const float*)d_in[1];
    const int*   pos = (const int*)d_in[2];
    float*       out = (float*)d_out;

    cudaFuncSetAttribute(fft_table_kernel, cudaFuncAttributeMaxDynamicSharedMemorySize, FFT_SMEM);
    cudaFuncSetAttribute(fft_cnt_kernel,   cudaFuncAttributeMaxDynamicSharedMemorySize, FFT_SMEM);
    cudaFuncSetAttribute(conv_kernel,      cudaFuncAttributeMaxDynamicSharedMemorySize, FFT_SMEM);

    hist_scan_kernel<<<Bc, 1024>>>(pos);
    fft_table_kernel<<<CPAIRS, FFT_THREADS, FFT_SMEM>>>(emb);
    fft_cnt_kernel<<<Bc, FFT_THREADS, FFT_SMEM>>>();
    conv_kernel<<<dim3(CPAIRS, Bc), FFT_THREADS, FFT_SMEM>>>();

    const int total_vec = Bc * Sc * Dc / 4;    // 1,048,576
    epilogue_kernel<<<total_vec / 256, 256>>>((const float4*)x, emb, pos, (float4*)out);
}

// round 6
// speedup vs baseline: 1.5214x; 1.0553x over previous
#include <cuda_runtime.h>
#include <cuda_bf16.h>
#include <cstdint>

// Problem constants (fixed shapes from the reference)
#define Bc     4
#define Sc     2048
#define Dc     512
#define Mc     2048          // clip range
#define Vc     4097          // 2M+1 table rows
#define PMAX   3000          // positions in [0, 3000)
#define NFFT   8192
#define CPAIRS (Dc/2)        // 256 complex-packed channel pairs
#define FFT_THREADS 512
#define LUT_N  1024                         // u = W^jm, jm < NFFT/8
#define PADN   (NFFT + (NFFT >> 5))         // 8448 u32 per buffer
#define MAP(i) ((i) + ((i) >> 5))           // bank-conflict-free pad (4B elems)
#define FFT_SMEM (2 * PADN * 4 + LUT_N * 8) // 75776 B -> 2 CTAs/SM

// ---------------------------------------------------------------------------
// Scratch (static device globals)
// ---------------------------------------------------------------------------
__device__ float    g_cnt[Bc][PMAX];        // per-batch position histogram
__device__ float    g_pre[Bc][PMAX];        // inclusive prefix sums
__device__ uint32_t g_CNT[Bc][NFFT];        // spectra of cnt (bf16x2: re,im)
__device__ uint32_t g_EMB[CPAIRS][NFFT];    // spectra of table column pairs
__device__ float    g_G[Bc][PMAX][Dc];      // interior conv result

// ---------------------------------------------------------------------------
// bf16x2 <-> float2 (re in low half, im in high half)
// ---------------------------------------------------------------------------
__device__ __forceinline__ float2 up(uint32_t v) {
    return make_float2(__uint_as_float(v << 16),
                       __uint_as_float(v & 0xFFFF0000u));
}
__device__ __forceinline__ uint32_t pk(float2 f) {
    uint32_t r;
    asm("cvt.rn.bf16x2.f32 %0, %1, %2;" : "=r"(r) : "f"(f.y), "f"(f.x));
    return r;
}

__device__ __forceinline__ float2 cmul(float2 a, float2 b) {
    return make_float2(a.x * b.x - a.y * b.y, a.x * b.y + a.y * b.x);
}
__device__ __forceinline__ float2 cadd(float2 a, float2 b) {
    return make_float2(a.x + b.x, a.y + b.y);
}
__device__ __forceinline__ float2 csub(float2 a, float2 b) {
    return make_float2(a.x - b.x, a.y - b.y);
}
// multiply by -i (forward) / +i (inverse)
template <bool INV>
__device__ __forceinline__ float2 mul_mi(float2 v) {
    return INV ? make_float2(-v.y, v.x) : make_float2(v.y, -v.x);
}
#define RSQRT2 0.70710678118654752f
template <bool INV>
__device__ __forceinline__ float2 mul_w1(float2 v) {
    return INV ? make_float2((v.x - v.y) * RSQRT2, (v.y + v.x) * RSQRT2)
               : make_float2((v.x + v.y) * RSQRT2, (v.y - v.x) * RSQRT2);
}
template <bool INV>
__device__ __forceinline__ float2 mul_w3(float2 v) {
    return INV ? make_float2((-v.x - v.y) * RSQRT2, (v.x - v.y) * RSQRT2)
               : make_float2((v.y - v.x) * RSQRT2, (-v.x - v.y) * RSQRT2);
}

// ---------------------------------------------------------------------------
// K1: histogram + inclusive prefix scan per batch
// ---------------------------------------------------------------------------
__global__ void hist_scan_kernel(const int* __restrict__ pos) {
    __shared__ float hist[3072];
    __shared__ float tsum[1024];
    const int b = blockIdx.x;
    const int t = threadIdx.x;

    for (int p = t; p < 3072; p += 1024) hist[p] = 0.0f;
    __syncthreads();
    for (int i = t; i < Sc; i += 1024)
        atomicAdd(&hist[pos[b * Sc + i]], 1.0f);
    __syncthreads();

    const float v0 = hist[3 * t + 0];
    const float v1 = hist[3 * t + 1];
    const float v2 = hist[3 * t + 2];
    const float s  = v0 + v1 + v2;
    tsum[t] = s;
    __syncthreads();
    for (int off = 1; off < 1024; off <<= 1) {
        const float add = (t >= off) ? tsum[t - off] : 0.0f;
        __syncthreads();
        tsum[t] += add;
        __syncthreads();
    }
    const float excl = tsum[t] - s;
    const int p0 = 3 * t;
    if (p0 + 0 < PMAX) { g_cnt[b][p0 + 0] = v0; g_pre[b][p0 + 0] = excl + v0; }
    if (p0 + 1 < PMAX) { g_cnt[b][p0 + 1] = v1; g_pre[b][p0 + 1] = excl + v0 + v1; }
    if (p0 + 2 < PMAX) { g_cnt[b][p0 + 2] = v2; g_pre[b][p0 + 2] = excl + v0 + v1 + v2; }
}

// ---------------------------------------------------------------------------
// Twiddle LUT (fp32): lut[t] = exp(-2*pi*i*t/NFFT), t in [0, NFFT/8)
// ---------------------------------------------------------------------------
__device__ __forceinline__ void build_lut(float2* lut) {
    const float w = -6.283185307179586f / (float)NFFT;
#pragma unroll
    for (int h = 0; h < LUT_N / FFT_THREADS; h++) {
        const int t = threadIdx.x + h * FFT_THREADS;
        float sn, cs;
        __sincosf(w * (float)t, &sn, &cs);
        lut[t] = make_float2(cs, sn);
    }
}

// ---------------------------------------------------------------------------
// Block FFT: Stockham autosort, 4 radix-8 stages + 1 twiddle-free radix-2.
// Data lives in smem as bf16x2; arithmetic fp32. 512 threads, 2 butterflies
// per thread per stage. Caller syncs after populating src + LUT.
// ---------------------------------------------------------------------------
template <bool INV>
__device__ uint32_t* block_fft8(uint32_t* b0, uint32_t* b1,
                                const float2* __restrict__ lut) {
    uint32_t* src = b0;
    uint32_t* dst = b1;
#pragma unroll
    for (int s = 0; s < 4; s++) {
        const int m = 1 << (3 * s);            // 1, 8, 64, 512
#pragma unroll
        for (int h = 0; h < 2; h++) {
            const int t  = threadIdx.x + h * 512;   // [0, 1024)
            const int k  = t & (m - 1);
            const int jm = t - k;

            const float2 x0 = up(src[MAP(t + 0 * 1024)]);
            const float2 x1 = up(src[MAP(t + 1 * 1024)]);
            const float2 x2 = up(src[MAP(t + 2 * 1024)]);
            const float2 x3 = up(src[MAP(t + 3 * 1024)]);
            const float2 x4 = up(src[MAP(t + 4 * 1024)]);
            const float2 x5 = up(src[MAP(t + 5 * 1024)]);
            const float2 x6 = up(src[MAP(t + 6 * 1024)]);
            const float2 x7 = up(src[MAP(t + 7 * 1024)]);

            const float2 t0 = cadd(x0, x4);
            const float2 t1 = csub(x0, x4);
            const float2 t2 = cadd(x2, x6);
            const float2 t3 = mul_mi<INV>(csub(x2, x6));
            const float2 E0 = cadd(t0, t2);
            const float2 E1 = cadd(t1, t3);
            const float2 E2 = csub(t0, t2);
            const float2 E3 = csub(t1, t3);
            const float2 s0 = cadd(x1, x5);
            const float2 s1 = csub(x1, x5);
            const float2 s2 = cadd(x3, x7);
            const float2 s3 = mul_mi<INV>(csub(x3, x7));
            const float2 O0 = cadd(s0, s2);
            const float2 O1 = mul_w1<INV>(cadd(s1, s3));
            const float2 O2 = mul_mi<INV>(csub(s0, s2));
            const float2 O3 = mul_w3<INV>(csub(s1, s3));

            float2 u = lut[jm];
            if (INV) u.y = -u.y;
            const float2 u2 = cmul(u, u);
            const float2 u3 = cmul(u2, u);
            const float2 u4 = cmul(u2, u2);
            const float2 u5 = cmul(u3, u2);
            const float2 u6 = cmul(u3, u3);
            const float2 u7 = cmul(u4, u3);

            const int ob = t + 7 * jm;          // 8*j*m + k
            dst[MAP(ob + 0 * m)] = pk(cadd(E0, O0));
            dst[MAP(ob + 1 * m)] = pk(cmul(u,  cadd(E1, O1)));
            dst[MAP(ob + 2 * m)] = pk(cmul(u2, cadd(E2, O2)));
            dst[MAP(ob + 3 * m)] = pk(cmul(u3, cadd(E3, O3)));
            dst[MAP(ob + 4 * m)] = pk(cmul(u4, csub(E0, O0)));
            dst[MAP(ob + 5 * m)] = pk(cmul(u5, csub(E1, O1)));
            dst[MAP(ob + 6 * m)] = pk(cmul(u6, csub(E2, O2)));
            dst[MAP(ob + 7 * m)] = pk(cmul(u7, csub(E3, O3)));
        }
        __syncthreads();
        uint32_t* tmp = src; src = dst; dst = tmp;
    }
    // final radix-2 stage: m = 4096, twiddle = 1
#pragma unroll
    for (int r = 0; r < 8; r++) {
        const int i = threadIdx.x + r * 512;
        const float2 a = up(src[MAP(i)]);
        const float2 b = up(src[MAP(i + 4096)]);
        dst[MAP(i)]        = pk(cadd(a, b));
        dst[MAP(i + 4096)] = pk(csub(a, b));
    }
    __syncthreads();
    return dst;
}

extern __shared__ uint32_t smu[];

// ---------------------------------------------------------------------------
// K2: forward FFT of table column pairs (channel 2c packed real, 2c+1 imag)
// ---------------------------------------------------------------------------
__global__ void __launch_bounds__(FFT_THREADS, 2)
fft_table_kernel(const float* __restrict__ emb) {
    const int c = blockIdx.x;
    uint32_t* b0  = smu;
    uint32_t* b1  = smu + PADN;
    float2*   lut = (float2*)(smu + 2 * PADN);
    build_lut(lut);
    for (int n = threadIdx.x; n < NFFT; n += FFT_THREADS) {
        float2 v = make_float2(0.0f, 0.0f);
        if (n < Vc) {
            v.x = emb[n * Dc + 2 * c + 0];
            v.y = emb[n * Dc + 2 * c + 1];
        }
        b0[MAP(n)] = pk(v);
    }
    __syncthreads();
    uint32_t* r = block_fft8<false>(b0, b1, lut);
    for (int n = threadIdx.x; n < NFFT; n += FFT_THREADS)
        g_EMB[c][n] = r[MAP(n)];
}

// ---------------------------------------------------------------------------
// K3: forward FFT of the per-batch count histograms
// ---------------------------------------------------------------------------
__global__ void __launch_bounds__(FFT_THREADS, 2)
fft_cnt_kernel() {
    const int b = blockIdx.x;
    uint32_t* b0  = smu;
    uint32_t* b1  = smu + PADN;
    float2*   lut = (float2*)(smu + 2 * PADN);
    build_lut(lut);
    for (int n = threadIdx.x; n < NFFT; n += FFT_THREADS) {
        float2 v = make_float2(0.0f, 0.0f);
        if (n < PMAX) v.x = g_cnt[b][n];
        b0[MAP(n)] = pk(v);
    }
    __syncthreads();
    uint32_t* r = block_fft8<false>(b0, b1, lut);
    for (int n = threadIdx.x; n < NFFT; n += FFT_THREADS)
        g_CNT[b][n] = r[MAP(n)];
}

// ---------------------------------------------------------------------------
// K4: pointwise spectral multiply + inverse FFT; extract y[q+M], q in [0,3000)
// ---------------------------------------------------------------------------
__global__ void __launch_bounds__(FFT_THREADS, 2)
conv_kernel() {
    const int c = blockIdx.x;
    const int b = blockIdx.y;
    uint32_t* b0  = smu;
    uint32_t* b1  = smu + PADN;
    float2*   lut = (float2*)(smu + 2 * PADN);
    build_lut(lut);
    const uint32_t* __restrict__ E = g_EMB[c];
    const uint32_t* __restrict__ T = g_CNT[b];
    for (int n = threadIdx.x; n < NFFT; n += FFT_THREADS) {
        const float2 e = up(E[n]);
        const float2 t = up(T[n]);
        b0[MAP(n)] = pk(cmul(e, t));
    }
    __syncthreads();
    uint32_t* r = block_fft8<true>(b0, b1, lut);
    const float inv = 1.0f / (float)NFFT;
    for (int q = threadIdx.x; q < PMAX; q += FFT_THREADS) {
        const float2 y = up(r[MAP(q + Mc)]);
        g_G[b][q][2 * c + 0] = y.x * inv;
        g_G[b][q][2 * c + 1] = y.y * inv;
    }
}

// ---------------------------------------------------------------------------
// K5: gather per output row + clamp-tail correction + add x, write out.
// ---------------------------------------------------------------------------
__global__ void epilogue_kernel(const float4* __restrict__ x,
                                const float*  __restrict__ emb,
                                const int*    __restrict__ pos,
                                float4*       __restrict__ out) {
    const int v = blockIdx.x * blockDim.x + threadIdx.x;
    const int d4  = v & (Dc / 4 - 1);
    const int row = v >> 7;
    const int b   = row >> 11;
    const int q   = pos[row];

    const float a0 = (float)Sc - g_pre[b][min(q + Mc, PMAX - 1)];
    const float a1 = (q >= Mc + 1) ? g_pre[b][q - Mc - 1] : 0.0f;
    const float invS = 1.0f / (float)Sc;

    const float4 xv = x[v];
    const float4 g  = *reinterpret_cast<const float4*>(&g_G[b][q][d4 * 4]);
    const float4 e0 = *reinterpret_cast<const float4*>(&emb[0 * Dc + d4 * 4]);
    const float4 e1 = *reinterpret_cast<const float4*>(&emb[(Vc - 1) * Dc + d4 * 4]);

    float4 o;
    o.x = xv.x + (g.x + a0 * e0.x + a1 * e1.x) * invS;
    o.y = xv.y + (g.y + a0 * e0.y + a1 * e1.y) * invS;
    o.z = xv.z + (g.z + a0 * e0.z + a1 * e1.z) * invS;
    o.w = xv.w + (g.w + a0 * e0.w + a1 * e1.w) * invS;
    out[v] = o;
}

// ---------------------------------------------------------------------------
// Launch
// ---------------------------------------------------------------------------
extern "C" void kernel_launch(void* const* d_in, const int* in_sizes, int n_in,
                              void* d_out, int out_size) {
    const float* x   = (const float*)d_in[0];
    const float* emb = (const float*)d_in[1];
    const int*   pos = (const int*)d_in[2];
    float*       out = (float*)d_out;

    cudaFuncSetAttribute(fft_table_kernel, cudaFuncAttributeMaxDynamicSharedMemorySize, FFT_SMEM);
    cudaFuncSetAttribute(fft_cnt_kernel,   cudaFuncAttributeMaxDynamicSharedMemorySize, FFT_SMEM);
    cudaFuncSetAttribute(conv_kernel,      cudaFuncAttributeMaxDynamicSharedMemorySize, FFT_SMEM);

    hist_scan_kernel<<<Bc, 1024>>>(pos);
    fft_table_kernel<<<CPAIRS, FFT_THREADS, FFT_SMEM>>>(emb);
    fft_cnt_kernel<<<Bc, FFT_THREADS, FFT_SMEM>>>();
    conv_kernel<<<dim3(CPAIRS, Bc), FFT_THREADS, FFT_SMEM>>>();

    const int total_vec = Bc * Sc * Dc / 4;    // 1,048,576
    epilogue_kernel<<<total_vec / 256, 256>>>((const float4*)x, emb, pos, (float4*)out);
}

// round 7
// speedup vs baseline: 1.5292x; 1.0051x over previous
#include <cuda_runtime.h>
#include <cuda_bf16.h>
#include <cstdint>

// Problem constants (fixed shapes from the reference)
#define Bc     4
#define Sc     2048
#define Dc     512
#define Mc     2048          // clip range
#define Vc     4097          // 2M+1 table rows
#define PMAX   3000          // positions in [0, 3000)
#define NFFT   8192
#define CPAIRS (Dc/2)        // 256 complex-packed channel pairs
#define FFT_THREADS 512
#define LUT_N  1024                         // u = W^jm, jm < NFFT/8
#define PADN   (NFFT + (NFFT >> 5))         // 8448 u32 per buffer
#define MAP(i) ((i) + ((i) >> 5))           // bank-conflict-free pad (4B elems)
#define FFT_SMEM (2 * PADN * 4 + LUT_N * 8) // 75776 B -> 2 CTAs/SM

// ---------------------------------------------------------------------------
// Scratch (static device globals)
// ---------------------------------------------------------------------------
__device__ float    g_cnt[Bc][PMAX];        // per-batch position histogram
__device__ float    g_pre[Bc][PMAX];        // inclusive prefix sums
__device__ uint32_t g_CNT[Bc][NFFT];        // spectra of cnt (bf16x2: re,im)
__device__ uint32_t g_EMB[CPAIRS][NFFT];    // spectra of table column pairs
__device__ float    g_G[Bc][PMAX][Dc];      // interior conv result

// ---------------------------------------------------------------------------
// bf16x2 <-> float2 (re in low half, im in high half)
// ---------------------------------------------------------------------------
__device__ __forceinline__ float2 up(uint32_t v) {
    return make_float2(__uint_as_float(v << 16),
                       __uint_as_float(v & 0xFFFF0000u));
}
__device__ __forceinline__ uint32_t pk(float2 f) {
    uint32_t r;
    asm("cvt.rn.bf16x2.f32 %0, %1, %2;" : "=r"(r) : "f"(f.y), "f"(f.x));
    return r;
}

__device__ __forceinline__ float2 cmul(float2 a, float2 b) {
    return make_float2(a.x * b.x - a.y * b.y, a.x * b.y + a.y * b.x);
}
__device__ __forceinline__ float2 cadd(float2 a, float2 b) {
    return make_float2(a.x + b.x, a.y + b.y);
}
__device__ __forceinline__ float2 csub(float2 a, float2 b) {
    return make_float2(a.x - b.x, a.y - b.y);
}
// multiply by -i (forward) / +i (inverse)
template <bool INV>
__device__ __forceinline__ float2 mul_mi(float2 v) {
    return INV ? make_float2(-v.y, v.x) : make_float2(v.y, -v.x);
}
#define RSQRT2 0.70710678118654752f
template <bool INV>
__device__ __forceinline__ float2 mul_w1(float2 v) {
    return INV ? make_float2((v.x - v.y) * RSQRT2, (v.y + v.x) * RSQRT2)
               : make_float2((v.x + v.y) * RSQRT2, (v.y - v.x) * RSQRT2);
}
template <bool INV>
__device__ __forceinline__ float2 mul_w3(float2 v) {
    return INV ? make_float2((-v.x - v.y) * RSQRT2, (v.x - v.y) * RSQRT2)
               : make_float2((v.y - v.x) * RSQRT2, (-v.x - v.y) * RSQRT2);
}

// ---------------------------------------------------------------------------
// K1: histogram + inclusive prefix scan per batch
// ---------------------------------------------------------------------------
__global__ void hist_scan_kernel(const int* __restrict__ pos) {
    __shared__ float hist[3072];
    __shared__ float tsum[1024];
    const int b = blockIdx.x;
    const int t = threadIdx.x;

    for (int p = t; p < 3072; p += 1024) hist[p] = 0.0f;
    __syncthreads();
    for (int i = t; i < Sc; i += 1024)
        atomicAdd(&hist[pos[b * Sc + i]], 1.0f);
    __syncthreads();

    const float v0 = hist[3 * t + 0];
    const float v1 = hist[3 * t + 1];
    const float v2 = hist[3 * t + 2];
    const float s  = v0 + v1 + v2;
    tsum[t] = s;
    __syncthreads();
    for (int off = 1; off < 1024; off <<= 1) {
        const float add = (t >= off) ? tsum[t - off] : 0.0f;
        __syncthreads();
        tsum[t] += add;
        __syncthreads();
    }
    const float excl = tsum[t] - s;
    const int p0 = 3 * t;
    if (p0 + 0 < PMAX) { g_cnt[b][p0 + 0] = v0; g_pre[b][p0 + 0] = excl + v0; }
    if (p0 + 1 < PMAX) { g_cnt[b][p0 + 1] = v1; g_pre[b][p0 + 1] = excl + v0 + v1; }
    if (p0 + 2 < PMAX) { g_cnt[b][p0 + 2] = v2; g_pre[b][p0 + 2] = excl + v0 + v1 + v2; }
}

// ---------------------------------------------------------------------------
// Twiddle LUT (fp32): lut[t] = exp(-2*pi*i*t/NFFT), t in [0, NFFT/8)
// ---------------------------------------------------------------------------
__device__ __forceinline__ void build_lut(float2* lut) {
    const float w = -6.283185307179586f / (float)NFFT;
#pragma unroll
    for (int h = 0; h < LUT_N / FFT_THREADS; h++) {
        const int t = threadIdx.x + h * FFT_THREADS;
        float sn, cs;
        __sincosf(w * (float)t, &sn, &cs);
        lut[t] = make_float2(cs, sn);
    }
}

// ---------------------------------------------------------------------------
// Block FFT: Stockham autosort, 4 radix-8 stages + 1 twiddle-free radix-2.
// Data lives in smem as bf16x2; arithmetic fp32. 512 threads, 2 butterflies
// per thread per stage. Caller syncs after populating src + LUT.
// ---------------------------------------------------------------------------
template <bool INV>
__device__ uint32_t* block_fft8(uint32_t* b0, uint32_t* b1,
                                const float2* __restrict__ lut) {
    uint32_t* src = b0;
    uint32_t* dst = b1;
#pragma unroll
    for (int s = 0; s < 4; s++) {
        const int m = 1 << (3 * s);            // 1, 8, 64, 512
#pragma unroll
        for (int h = 0; h < 2; h++) {
            const int t  = threadIdx.x + h * 512;   // [0, 1024)
            const int k  = t & (m - 1);
            const int jm = t - k;

            const float2 x0 = up(src[MAP(t + 0 * 1024)]);
            const float2 x1 = up(src[MAP(t + 1 * 1024)]);
            const float2 x2 = up(src[MAP(t + 2 * 1024)]);
            const float2 x3 = up(src[MAP(t + 3 * 1024)]);
            const float2 x4 = up(src[MAP(t + 4 * 1024)]);
            const float2 x5 = up(src[MAP(t + 5 * 1024)]);
            const float2 x6 = up(src[MAP(t + 6 * 1024)]);
            const float2 x7 = up(src[MAP(t + 7 * 1024)]);

            const float2 t0 = cadd(x0, x4);
            const float2 t1 = csub(x0, x4);
            const float2 t2 = cadd(x2, x6);
            const float2 t3 = mul_mi<INV>(csub(x2, x6));
            const float2 E0 = cadd(t0, t2);
            const float2 E1 = cadd(t1, t3);
            const float2 E2 = csub(t0, t2);
            const float2 E3 = csub(t1, t3);
            const float2 s0 = cadd(x1, x5);
            const float2 s1 = csub(x1, x5);
            const float2 s2 = cadd(x3, x7);
            const float2 s3 = mul_mi<INV>(csub(x3, x7));
            const float2 O0 = cadd(s0, s2);
            const float2 O1 = mul_w1<INV>(cadd(s1, s3));
            const float2 O2 = mul_mi<INV>(csub(s0, s2));
            const float2 O3 = mul_w3<INV>(csub(s1, s3));

            float2 u = lut[jm];
            if (INV) u.y = -u.y;
            const float2 u2 = cmul(u, u);
            const float2 u3 = cmul(u2, u);
            const float2 u4 = cmul(u2, u2);
            const float2 u5 = cmul(u3, u2);
            const float2 u6 = cmul(u3, u3);
            const float2 u7 = cmul(u4, u3);

            const int ob = t + 7 * jm;          // 8*j*m + k
            dst[MAP(ob + 0 * m)] = pk(cadd(E0, O0));
            dst[MAP(ob + 1 * m)] = pk(cmul(u,  cadd(E1, O1)));
            dst[MAP(ob + 2 * m)] = pk(cmul(u2, cadd(E2, O2)));
            dst[MAP(ob + 3 * m)] = pk(cmul(u3, cadd(E3, O3)));
            dst[MAP(ob + 4 * m)] = pk(cmul(u4, csub(E0, O0)));
            dst[MAP(ob + 5 * m)] = pk(cmul(u5, csub(E1, O1)));
            dst[MAP(ob + 6 * m)] = pk(cmul(u6, csub(E2, O2)));
            dst[MAP(ob + 7 * m)] = pk(cmul(u7, csub(E3, O3)));
        }
        __syncthreads();
        uint32_t* tmp = src; src = dst; dst = tmp;
    }
    // final radix-2 stage: m = 4096, twiddle = 1
#pragma unroll
    for (int r = 0; r < 8; r++) {
        const int i = threadIdx.x + r * 512;
        const float2 a = up(src[MAP(i)]);
        const float2 b = up(src[MAP(i + 4096)]);
        dst[MAP(i)]        = pk(cadd(a, b));
        dst[MAP(i + 4096)] = pk(csub(a, b));
    }
    __syncthreads();
    return dst;
}

extern __shared__ uint32_t smu[];

// ---------------------------------------------------------------------------
// K2: forward FFT of table column pairs (channel 2c packed real, 2c+1 imag)
// ---------------------------------------------------------------------------
__global__ void __launch_bounds__(FFT_THREADS, 2)
fft_table_kernel(const float* __restrict__ emb) {
    const int c = blockIdx.x;
    uint32_t* b0  = smu;
    uint32_t* b1  = smu + PADN;
    float2*   lut = (float2*)(smu + 2 * PADN);
    build_lut(lut);
    for (int n = threadIdx.x; n < NFFT; n += FFT_THREADS) {
        float2 v = make_float2(0.0f, 0.0f);
        if (n < Vc) {
            v.x = emb[n * Dc + 2 * c + 0];
            v.y = emb[n * Dc + 2 * c + 1];
        }
        b0[MAP(n)] = pk(v);
    }
    __syncthreads();
    uint32_t* r = block_fft8<false>(b0, b1, lut);
    for (int n = threadIdx.x; n < NFFT; n += FFT_THREADS)
        g_EMB[c][n] = r[MAP(n)];
}

// ---------------------------------------------------------------------------
// K3: forward FFT of the per-batch count histograms
// ---------------------------------------------------------------------------
__global__ void __launch_bounds__(FFT_THREADS, 2)
fft_cnt_kernel() {
    const int b = blockIdx.x;
    uint32_t* b0  = smu;
    uint32_t* b1  = smu + PADN;
    float2*   lut = (float2*)(smu + 2 * PADN);
    build_lut(lut);
    for (int n = threadIdx.x; n < NFFT; n += FFT_THREADS) {
        float2 v = make_float2(0.0f, 0.0f);
        if (n < PMAX) v.x = g_cnt[b][n];
        b0[MAP(n)] = pk(v);
    }
    __syncthreads();
    uint32_t* r = block_fft8<false>(b0, b1, lut);
    for (int n = threadIdx.x; n < NFFT; n += FFT_THREADS)
        g_CNT[b][n] = r[MAP(n)];
}

// ---------------------------------------------------------------------------
// K4: pointwise spectral multiply + inverse FFT; extract y[q+M], q in [0,3000)
// ---------------------------------------------------------------------------
__global__ void __launch_bounds__(FFT_THREADS, 2)
conv_kernel() {
    const int c = blockIdx.x;
    const int b = blockIdx.y;
    uint32_t* b0  = smu;
    uint32_t* b1  = smu + PADN;
    float2*   lut = (float2*)(smu + 2 * PADN);
    build_lut(lut);
    const uint32_t* __restrict__ E = g_EMB[c];
    const uint32_t* __restrict__ T = g_CNT[b];
    for (int n = threadIdx.x; n < NFFT; n += FFT_THREADS) {
        const float2 e = up(E[n]);
        const float2 t = up(T[n]);
        b0[MAP(n)] = pk(cmul(e, t));
    }
    __syncthreads();
    uint32_t* r = block_fft8<true>(b0, b1, lut);
    const float inv = 1.0f / (float)NFFT;
    for (int q = threadIdx.x; q < PMAX; q += FFT_THREADS) {
        const float2 y = up(r[MAP(q + Mc)]);
        g_G[b][q][2 * c + 0] = y.x * inv;
        g_G[b][q][2 * c + 1] = y.y * inv;
    }
}

// ---------------------------------------------------------------------------
// K5: gather per output row + clamp-tail correction + add x, write out.
// ---------------------------------------------------------------------------
__global__ void epilogue_kernel(const float4* __restrict__ x,
                                const float*  __restrict__ emb,
                                const int*    __restrict__ pos,
                                float4*       __restrict__ out) {
    const int v = blockIdx.x * blockDim.x + threadIdx.x;
    const int d4  = v & (Dc / 4 - 1);
    const int row = v >> 7;
    const int b   = row >> 11;
    const int q   = pos[row];

    const float a0 = (float)Sc - g_pre[b][min(q + Mc, PMAX - 1)];
    const float a1 = (q >= Mc + 1) ? g_pre[b][q - Mc - 1] : 0.0f;
    const float invS = 1.0f / (float)Sc;

    const float4 xv = x[v];
    const float4 g  = *reinterpret_cast<const float4*>(&g_G[b][q][d4 * 4]);
    const float4 e0 = *reinterpret_cast<const float4*>(&emb[0 * Dc + d4 * 4]);
    const float4 e1 = *reinterpret_cast<const float4*>(&emb[(Vc - 1) * Dc + d4 * 4]);

    float4 o;
    o.x = xv.x + (g.x + a0 * e0.x + a1 * e1.x) * invS;
    o.y = xv.y + (g.y + a0 * e0.y + a1 * e1.y) * invS;
    o.z = xv.z + (g.z + a0 * e0.z + a1 * e1.z) * invS;
    o.w = xv.w + (g.w + a0 * e0.w + a1 * e1.w) * invS;
    out[v] = o;
}

// ---------------------------------------------------------------------------
// Launch
// ---------------------------------------------------------------------------
extern "C" void kernel_launch(void* const* d_in, const int* in_sizes, int n_in,
                              void* d_out, int out_size) {
    const float* x   = (const float*)d_in[0];
    const float* emb = (const float*)d_in[1];
    const int*   pos = (const int*)d_in[2];
    float*       out = (float*)d_out;

    cudaFuncSetAttribute(fft_table_kernel, cudaFuncAttributeMaxDynamicSharedMemorySize, FFT_SMEM);
    cudaFuncSetAttribute(fft_cnt_kernel,   cudaFuncAttributeMaxDynamicSharedMemorySize, FFT_SMEM);
    cudaFuncSetAttribute(conv_kernel,      cudaFuncAttributeMaxDynamicSharedMemorySize, FFT_SMEM);

    hist_scan_kernel<<<Bc, 1024>>>(pos);
    fft_table_kernel<<<CPAIRS, FFT_THREADS, FFT_SMEM>>>(emb);
    fft_cnt_kernel<<<Bc, FFT_THREADS, FFT_SMEM>>>();
    conv_kernel<<<dim3(CPAIRS, Bc), FFT_THREADS, FFT_SMEM>>>();

    const int total_vec = Bc * Sc * Dc / 4;    // 1,048,576
    epilogue_kernel<<<total_vec / 256, 256>>>((const float4*)x, emb, pos, (float4*)out);
}